// round 2
// baseline (speedup 1.0000x reference)
#include <cuda_runtime.h>
#include <cuda_fp16.h>
#include <cstdint>

// ---------------- static scratch (no allocs allowed) ----------------
__device__ __half g_xh[67108864];      // x in fp16, [n][c][h][w]      134 MB
__device__ __half g_q[8388608];        // q fp16 (pass-specific layout) 16.8 MB
__device__ __half g_k[8388608];        // k fp16                        16.8 MB
__device__ __half g_v[67108864];       // v fp16 [n][c][h*w]            134 MB
__device__ float  g_E[1048576];        // energy fp32 [n][512][512]     4 MB
__device__ __half g_attn[1048576];     // attn fp16                     2 MB
__device__ __half g_wh[2][4096];       // v-weights fp16 (time, freq)

// ---------------- small helpers ----------------
__device__ __forceinline__ uint32_t smem_u32(const void* p) {
    return (uint32_t)__cvta_generic_to_shared(p);
}
__device__ __forceinline__ void cp16(uint32_t dst, const void* src) {
    asm volatile("cp.async.cg.shared.global [%0], [%1], 16;" :: "r"(dst), "l"(src));
}
__device__ __forceinline__ void cp_commit() {
    asm volatile("cp.async.commit_group;");
}
__device__ __forceinline__ void ldm_x4(uint32_t addr, uint32_t& r0, uint32_t& r1, uint32_t& r2, uint32_t& r3) {
    asm volatile("ldmatrix.sync.aligned.m8n8.x4.shared.b16 {%0,%1,%2,%3}, [%4];"
                 : "=r"(r0), "=r"(r1), "=r"(r2), "=r"(r3) : "r"(addr));
}
__device__ __forceinline__ void ldm_x4t(uint32_t addr, uint32_t& r0, uint32_t& r1, uint32_t& r2, uint32_t& r3) {
    asm volatile("ldmatrix.sync.aligned.m8n8.x4.trans.shared.b16 {%0,%1,%2,%3}, [%4];"
                 : "=r"(r0), "=r"(r1), "=r"(r2), "=r"(r3) : "r"(addr));
}
__device__ __forceinline__ void mma16816(float* c, const uint32_t* a, const uint32_t* b) {
    asm volatile("mma.sync.aligned.m16n8k16.row.col.f32.f16.f16.f32 "
                 "{%0,%1,%2,%3},{%4,%5,%6,%7},{%8,%9},{%0,%1,%2,%3};"
                 : "+f"(c[0]), "+f"(c[1]), "+f"(c[2]), "+f"(c[3])
                 : "r"(a[0]), "r"(a[1]), "r"(a[2]), "r"(a[3]), "r"(b[0]), "r"(b[1]));
}

// ---------------- converts ----------------
__global__ void k_convert_x(const float4* __restrict__ x) {
    int i = blockIdx.x * blockDim.x + threadIdx.x;   // 16,777,216 float4s
    float4 f = x[i];
    __half2* o = reinterpret_cast<__half2*>(g_xh);
    o[2 * i + 0] = __floats2half2_rn(f.x, f.y);
    o[2 * i + 1] = __floats2half2_rn(f.z, f.w);
}

__global__ void k_convert_w(const float* __restrict__ tvw, const float* __restrict__ fvw) {
    int i = blockIdx.x * blockDim.x + threadIdx.x;   // 4096
    g_wh[0][i] = __float2half(tvw[i]);
    g_wh[1][i] = __float2half(fvw[i]);
}

// ---------------- q/k projection (SIMT, fp32 accumulate) ----------------
// out layout: g_q[n*2097152 + o*sC + h*sH + w]  (time: sC=512,sH=4096; freq: sC=262144,sH=512)
__global__ __launch_bounds__(256) void k_proj_qk(
    const float* __restrict__ wq, const float* __restrict__ bq,
    const float* __restrict__ wk, const float* __restrict__ bk,
    int sC, int sH)
{
    __shared__ float swq[512], swk[512], sbq[8], sbk[8];
    int tid = threadIdx.x;
    for (int i = tid; i < 512; i += 256) { swq[i] = wq[i]; swk[i] = wk[i]; }
    if (tid < 8) { sbq[tid] = bq[tid]; sbk[tid] = bk[tid]; }
    __syncthreads();

    int pix = blockIdx.x * 256 + tid;        // 4*512*512 pixels
    int n = pix >> 18;
    int rem = pix & 262143;
    int h = rem >> 9, w = rem & 511;

    long long base = (long long)n * 16777216 + (long long)h * 512 + w;
    float xv[64];
#pragma unroll
    for (int c = 0; c < 64; c++) xv[c] = __half2float(g_xh[base + (long long)c * 262144]);

    long long ob = (long long)n * 2097152 + (long long)h * sH + w;
#pragma unroll
    for (int o = 0; o < 8; o++) {
        float aq = sbq[o], ak = sbk[o];
#pragma unroll
        for (int c = 0; c < 64; c++) {
            aq += xv[c] * swq[o * 64 + c];
            ak += xv[c] * swk[o * 64 + c];
        }
        g_q[ob + (long long)o * sC] = __float2half(aq);
        g_k[ob + (long long)o * sC] = __float2half(ak);
    }
}

// ---------------- softmax over rows of 512 (fp32 in -> fp16 out) ----------------
__global__ __launch_bounds__(256) void k_softmax() {
    int r = blockIdx.x, t = threadIdx.x;
    const float* e = g_E + (long long)r * 512;
    float v0 = e[t], v1 = e[t + 256];

    __shared__ float red[8];
    float m = fmaxf(v0, v1);
#pragma unroll
    for (int o = 16; o; o >>= 1) m = fmaxf(m, __shfl_xor_sync(0xffffffffu, m, o));
    if ((t & 31) == 0) red[t >> 5] = m;
    __syncthreads();
    float M = red[0];
#pragma unroll
    for (int i = 1; i < 8; i++) M = fmaxf(M, red[i]);
    __syncthreads();

    float e0 = __expf(v0 - M), e1 = __expf(v1 - M);
    float s = e0 + e1;
#pragma unroll
    for (int o = 16; o; o >>= 1) s += __shfl_xor_sync(0xffffffffu, s, o);
    if ((t & 31) == 0) red[t >> 5] = s;
    __syncthreads();
    float S = 0.f;
#pragma unroll
    for (int i = 0; i < 8; i++) S += red[i];
    float inv = 1.f / S;

    __half* a = g_attn + (long long)r * 512;
    a[t] = __float2half(e0 * inv);
    a[t + 256] = __float2half(e1 * inv);
}

// ---------------- generic fp16 tensor-core GEMM ----------------
// C[M,N] = A op B.  OPA: 0 -> A[m][k] (lda over m-rows), 1 -> A[k][m] (lda over k-rows)
//                   OPB: 0 -> B[k][n],                   1 -> B[n][k]
// EPI: 0: Cf=acc   1: Ch=half(acc+bias[row])   2: Cf=3*Xin+g*acc   3: Cf+=g*acc
// BMODE: 0: offA=z*bsA   1: offA=(z>>6)*bsA
template<int BM, int BN, int OPA, int OPB, int EPI, int BMODE>
__global__ __launch_bounds__(256) void k_gemm(
    const __half* __restrict__ Ag, const __half* __restrict__ Bg,
    float* __restrict__ Cf, __half* __restrict__ Ch,
    const float* __restrict__ Xin, const float* __restrict__ aux,
    int K, int lda, int ldb, int ldc,
    long long bsA, long long bsB, long long bsC)
{
    constexpr int BK = 32;
    constexpr int WM_ = BM / 32;      // warps along M
    constexpr int WNT = BN / (8 / WM_);
    constexpr int NF = WNT / 8;
    constexpr int AROWS = OPA ? BK : BM;
    constexpr int ACOLS = (OPA ? BM : BK) + 8;
    constexpr int BROWS = OPB ? BN : BK;
    constexpr int BCOLS = (OPB ? BK : BN) + 8;

    __shared__ __align__(16) __half As[2][AROWS][ACOLS];
    __shared__ __align__(16) __half Bs[2][BROWS][BCOLS];

    const int tid = threadIdx.x;
    const int warp = tid >> 5, lane = tid & 31;
    const int wm = warp % WM_, wn = warp / WM_;
    const int tr = lane & 7, tg = lane >> 3;

    const int z = blockIdx.z;
    const int n_base = blockIdx.x * BN;
    const int m_base = blockIdx.y * BM;

    long long offA = (BMODE == 1 ? (long long)(z >> 6) : (long long)z) * bsA;
    const __half* Ab = Ag + offA + (OPA ? (long long)m_base : (long long)m_base * lda);
    const __half* Bb = Bg + (long long)z * bsB + (OPB ? (long long)n_base * ldb : (long long)n_base);

    const int KT = K / BK;
    uint32_t aS = smem_u32(&As[0][0][0]);
    uint32_t bS = smem_u32(&Bs[0][0][0]);

    auto load_tile = [&](int st, int kt) {
        {
            constexpr int CH = (OPA ? BM : BK) / 8;
            constexpr int TOT = AROWS * CH;
#pragma unroll
            for (int c0 = 0; c0 < TOT; c0 += 256) {
                int c = c0 + tid;
                int r = c / CH, s = (c % CH) * 8;
                const __half* src = OPA ? (Ab + (long long)(kt * BK + r) * lda + s)
                                        : (Ab + (long long)r * lda + kt * BK + s);
                cp16(aS + (uint32_t)(((st * AROWS + r) * ACOLS + s) * 2), src);
            }
        }
        {
            constexpr int CH = (OPB ? BK : BN) / 8;
            constexpr int TOT = BROWS * CH;
#pragma unroll
            for (int c0 = 0; c0 < TOT; c0 += 256) {
                int c = c0 + tid;
                int r = c / CH, s = (c % CH) * 8;
                const __half* src = OPB ? (Bb + (long long)r * ldb + kt * BK + s)
                                        : (Bb + (long long)(kt * BK + r) * ldb + s);
                cp16(bS + (uint32_t)(((st * BROWS + r) * BCOLS + s) * 2), src);
            }
        }
        cp_commit();
    };

    float acc[2][NF][4];
#pragma unroll
    for (int mi = 0; mi < 2; mi++)
#pragma unroll
        for (int ni = 0; ni < NF; ni++)
#pragma unroll
            for (int j = 0; j < 4; j++) acc[mi][ni][j] = 0.f;

    load_tile(0, 0);

    for (int kt = 0; kt < KT; kt++) {
        if (kt + 1 < KT) {
            load_tile((kt + 1) & 1, kt + 1);
            asm volatile("cp.async.wait_group 1;" ::: "memory");
        } else {
            asm volatile("cp.async.wait_group 0;" ::: "memory");
        }
        __syncthreads();

        const int st = kt & 1;
#pragma unroll
        for (int ks = 0; ks < 2; ks++) {
            const int k0 = ks * 16;
            uint32_t a[2][4];
#pragma unroll
            for (int mi = 0; mi < 2; mi++) {
                int r0 = wm * 32 + mi * 16;
                if (OPA == 0) {
                    int row = r0 + tr + (tg & 1) * 8, col = k0 + (tg >> 1) * 8;
                    ldm_x4(aS + (uint32_t)(((st * AROWS + row) * ACOLS + col) * 2),
                           a[mi][0], a[mi][1], a[mi][2], a[mi][3]);
                } else {
                    int row = k0 + tr + (tg >> 1) * 8, col = r0 + (tg & 1) * 8;
                    ldm_x4t(aS + (uint32_t)(((st * AROWS + row) * ACOLS + col) * 2),
                            a[mi][0], a[mi][1], a[mi][2], a[mi][3]);
                }
            }
            uint32_t b[NF][2];
#pragma unroll
            for (int np = 0; np < NF / 2; np++) {
                int c0 = wn * WNT + np * 16;
                uint32_t q0, q1, q2, q3;
                if (OPB == 0) {
                    int row = k0 + tr + (tg & 1) * 8, col = c0 + (tg >> 1) * 8;
                    ldm_x4t(bS + (uint32_t)(((st * BROWS + row) * BCOLS + col) * 2), q0, q1, q2, q3);
                } else {
                    int row = c0 + tr + (tg >> 1) * 8, col = k0 + (tg & 1) * 8;
                    ldm_x4(bS + (uint32_t)(((st * BROWS + row) * BCOLS + col) * 2), q0, q1, q2, q3);
                }
                b[np * 2][0] = q0; b[np * 2][1] = q1;
                b[np * 2 + 1][0] = q2; b[np * 2 + 1][1] = q3;
            }
#pragma unroll
            for (int mi = 0; mi < 2; mi++)
#pragma unroll
                for (int ni = 0; ni < NF; ni++)
                    mma16816(acc[mi][ni], a[mi], b[ni]);
        }
        __syncthreads();
    }

    // epilogue
    long long offC = (long long)z * bsC;
    float g = (EPI == 2 || EPI == 3) ? aux[0] : 0.f;
#pragma unroll
    for (int mi = 0; mi < 2; mi++) {
        int r0 = m_base + wm * 32 + mi * 16 + (lane >> 2);
#pragma unroll
        for (int ni = 0; ni < NF; ni++) {
            int c0 = n_base + wn * WNT + ni * 8 + (lane & 3) * 2;
            float* ac = acc[mi][ni];
#pragma unroll
            for (int j = 0; j < 4; j++) {
                int r = r0 + (j >> 1) * 8;
                int c = c0 + (j & 1);
                long long idx = offC + (long long)r * ldc + c;
                float v = ac[j];
                if (EPI == 0) Cf[idx] = v;
                else if (EPI == 1) Ch[idx] = __float2half(v + aux[r]);
                else if (EPI == 2) Cf[idx] = 3.f * Xin[idx] + g * v;
                else Cf[idx] += g * v;
            }
        }
    }
}

// ---------------- host ----------------
extern "C" void kernel_launch(void* const* d_in, const int* in_sizes, int n_in,
                              void* d_out, int out_size)
{
    const float* x    = (const float*)d_in[0];
    const float* tq_w = (const float*)d_in[1];
    const float* tq_b = (const float*)d_in[2];
    const float* tk_w = (const float*)d_in[3];
    const float* tk_b = (const float*)d_in[4];
    const float* tv_w = (const float*)d_in[5];
    const float* tv_b = (const float*)d_in[6];
    const float* t_g  = (const float*)d_in[7];
    const float* fq_w = (const float*)d_in[8];
    const float* fq_b = (const float*)d_in[9];
    const float* fk_w = (const float*)d_in[10];
    const float* fk_b = (const float*)d_in[11];
    const float* fv_w = (const float*)d_in[12];
    const float* fv_b = (const float*)d_in[13];
    const float* f_g  = (const float*)d_in[14];
    float* out = (float*)d_out;

    __half *xh, *q, *k, *v, *attn, *wh;
    float* E;
    cudaGetSymbolAddress((void**)&xh, g_xh);
    cudaGetSymbolAddress((void**)&q, g_q);
    cudaGetSymbolAddress((void**)&k, g_k);
    cudaGetSymbolAddress((void**)&v, g_v);
    cudaGetSymbolAddress((void**)&E, g_E);
    cudaGetSymbolAddress((void**)&attn, g_attn);
    cudaGetSymbolAddress((void**)&wh, g_wh);

    k_convert_x<<<65536, 256>>>((const float4*)x);
    k_convert_w<<<16, 256>>>(tv_w, fv_w);

    // ---- time attention ----
    // q/k transposed: [n][h][c8][w]  (sC=512, sH=4096)
    k_proj_qk<<<4096, 256>>>(tq_w, tq_b, tk_w, tk_b, 512, 4096);
    // v = W @ xh (per n), M=64, N=262144, K=64
    k_gemm<64, 128, 0, 0, 1, 0><<<dim3(2048, 1, 4), 256>>>(
        wh, xh, nullptr, v, nullptr, tv_b,
        64, 64, 262144, 262144, 0LL, 16777216LL, 16777216LL);
    // energy: NT, M=N=512, K=4096
    k_gemm<128, 64, 0, 1, 0, 0><<<dim3(8, 4, 4), 256>>>(
        q, k, E, nullptr, nullptr, nullptr,
        4096, 4096, 4096, 512, 2097152LL, 2097152LL, 262144LL);
    k_softmax<<<2048, 256>>>();
    // out: NN, batch z=(n,c): out = 3x + g*attn@v
    k_gemm<128, 128, 0, 0, 2, 1><<<dim3(4, 4, 256), 256>>>(
        attn, v, out, nullptr, x, t_g,
        512, 512, 512, 512, 262144LL, 262144LL, 262144LL);

    // ---- freq attention ----
    // q/k natural: [n][c8][h][w]  (sC=262144, sH=512)
    k_proj_qk<<<4096, 256>>>(fq_w, fq_b, fk_w, fk_b, 262144, 512);
    k_gemm<64, 128, 0, 0, 1, 0><<<dim3(2048, 1, 4), 256>>>(
        wh + 4096, xh, nullptr, v, nullptr, fv_b,
        64, 64, 262144, 262144, 0LL, 16777216LL, 16777216LL);
    // energy: TN, M=N=512, K=4096
    k_gemm<128, 64, 1, 0, 0, 0><<<dim3(8, 4, 4), 256>>>(
        q, k, E, nullptr, nullptr, nullptr,
        4096, 512, 512, 512, 2097152LL, 2097152LL, 262144LL);
    k_softmax<<<2048, 256>>>();
    // out: NT, per n: out += g * v @ attn^T, M=32768, N=512, K=512
    k_gemm<128, 128, 0, 1, 3, 0><<<dim3(4, 256, 4), 256>>>(
        v, attn, out, nullptr, nullptr, f_g,
        512, 512, 512, 512, 16777216LL, 262144LL, 16777216LL);
}

// round 3
// speedup vs baseline: 1.5591x; 1.5591x over previous
#include <cuda_runtime.h>
#include <cuda_fp16.h>
#include <cstdint>

// ---------------- static scratch ----------------
__device__ __half g_xh[67108864];      // x fp16 [n][c][h][w]          134 MB
__device__ __half g_qt[8388608];       // time q  [n][h][c8][w]
__device__ __half g_kt[8388608];       // time k  [n][h][c8][w]
__device__ __half g_qf[8388608];       // freq q  [n][c8][h][w]
__device__ __half g_kf[8388608];       // freq k  [n][c8][h][w]
__device__ __half g_vt[67108864];      // time v  [n][c][h][w]         134 MB
__device__ __half g_vf[67108864];      // freq v  [n][c][h][w]         134 MB
__device__ float  g_E[1048576];        // energy fp32 [n][512][512]
__device__ __half g_attn[1048576];     // attn fp16
__device__ __half g_wqk[2048];         // stacked [32][64]: tq,tk,fq,fk
__device__ __half g_wv[8192];          // stacked [128][64]: tv,fv
__device__ float  g_bqk[32];
__device__ float  g_bv[128];

// ---------------- helpers ----------------
__device__ __forceinline__ uint32_t smem_u32(const void* p) {
    return (uint32_t)__cvta_generic_to_shared(p);
}
__device__ __forceinline__ void cp16(uint32_t dst, const void* src) {
    asm volatile("cp.async.cg.shared.global [%0], [%1], 16;" :: "r"(dst), "l"(src));
}
__device__ __forceinline__ void cp_commit() {
    asm volatile("cp.async.commit_group;");
}
__device__ __forceinline__ void ldm_x4(uint32_t addr, uint32_t& r0, uint32_t& r1, uint32_t& r2, uint32_t& r3) {
    asm volatile("ldmatrix.sync.aligned.m8n8.x4.shared.b16 {%0,%1,%2,%3}, [%4];"
                 : "=r"(r0), "=r"(r1), "=r"(r2), "=r"(r3) : "r"(addr));
}
__device__ __forceinline__ void ldm_x4t(uint32_t addr, uint32_t& r0, uint32_t& r1, uint32_t& r2, uint32_t& r3) {
    asm volatile("ldmatrix.sync.aligned.m8n8.x4.trans.shared.b16 {%0,%1,%2,%3}, [%4];"
                 : "=r"(r0), "=r"(r1), "=r"(r2), "=r"(r3) : "r"(addr));
}
__device__ __forceinline__ void mma16816(float* c, const uint32_t* a, const uint32_t* b) {
    asm volatile("mma.sync.aligned.m16n8k16.row.col.f32.f16.f16.f32 "
                 "{%0,%1,%2,%3},{%4,%5,%6,%7},{%8,%9},{%0,%1,%2,%3};"
                 : "+f"(c[0]), "+f"(c[1]), "+f"(c[2]), "+f"(c[3])
                 : "r"(a[0]), "r"(a[1]), "r"(a[2]), "r"(a[3]), "r"(b[0]), "r"(b[1]));
}

// ---------------- converts / packing ----------------
__global__ void k_convert_x(const float4* __restrict__ x) {
    int i = blockIdx.x * blockDim.x + threadIdx.x;   // 16,777,216 float4s
    float4 f = x[i];
    __half2* o = reinterpret_cast<__half2*>(g_xh);
    o[2 * i + 0] = __floats2half2_rn(f.x, f.y);
    o[2 * i + 1] = __floats2half2_rn(f.z, f.w);
}

__global__ void k_pack_w(
    const float* __restrict__ tqw, const float* __restrict__ tkw,
    const float* __restrict__ fqw, const float* __restrict__ fkw,
    const float* __restrict__ tqb, const float* __restrict__ tkb,
    const float* __restrict__ fqb, const float* __restrict__ fkb,
    const float* __restrict__ tvw, const float* __restrict__ fvw,
    const float* __restrict__ tvb, const float* __restrict__ fvb)
{
    int t = threadIdx.x;   // 256
    for (int i = t; i < 512; i += 256) {
        g_wqk[i]        = __float2half(tqw[i]);
        g_wqk[512 + i]  = __float2half(tkw[i]);
        g_wqk[1024 + i] = __float2half(fqw[i]);
        g_wqk[1536 + i] = __float2half(fkw[i]);
    }
    for (int i = t; i < 4096; i += 256) {
        g_wv[i]        = __float2half(tvw[i]);
        g_wv[4096 + i] = __float2half(fvw[i]);
    }
    if (t < 8)  { g_bqk[t] = tqb[t]; g_bqk[8 + t] = tkb[t]; g_bqk[16 + t] = fqb[t]; g_bqk[24 + t] = fkb[t]; }
    if (t < 64) { g_bv[t] = tvb[t]; g_bv[64 + t] = fvb[t]; }
}

// ---------------- softmax over rows of 512 ----------------
__global__ __launch_bounds__(256) void k_softmax() {
    int r = blockIdx.x, t = threadIdx.x;
    const float* e = g_E + (long long)r * 512;
    float v0 = e[t], v1 = e[t + 256];

    __shared__ float red[8];
    float m = fmaxf(v0, v1);
#pragma unroll
    for (int o = 16; o; o >>= 1) m = fmaxf(m, __shfl_xor_sync(0xffffffffu, m, o));
    if ((t & 31) == 0) red[t >> 5] = m;
    __syncthreads();
    float M = red[0];
#pragma unroll
    for (int i = 1; i < 8; i++) M = fmaxf(M, red[i]);
    __syncthreads();

    float e0 = __expf(v0 - M), e1 = __expf(v1 - M);
    float s = e0 + e1;
#pragma unroll
    for (int o = 16; o; o >>= 1) s += __shfl_xor_sync(0xffffffffu, s, o);
    if ((t & 31) == 0) red[t >> 5] = s;
    __syncthreads();
    float S = 0.f;
#pragma unroll
    for (int i = 0; i < 8; i++) S += red[i];
    float inv = 1.f / S;

    __half* a = g_attn + (long long)r * 512;
    a[t] = __float2half(e0 * inv);
    a[t + 256] = __float2half(e1 * inv);
}

// ---------------- generic fp16 tensor-core GEMM ----------------
// OPA: 0 -> A[m][k], 1 -> A[k][m].   OPB: 0 -> B[k][n], 1 -> B[n][k].
// EPI: 0 energy fp32 | 2 out=3x+g*acc | 3 out+=g*acc | 4 qk-scatter | 5 v-dual
// BMODE: 0 -> offA=z*bsA  |  1 -> offA=(z>>6)*bsA
template<int BM, int BN, int BK, int OPA, int OPB, int EPI, int BMODE>
__global__ __launch_bounds__(256) void k_gemm(
    const __half* __restrict__ Ag, const __half* __restrict__ Bg,
    void* P0, void* P1, void* P2, void* P3,
    const float* __restrict__ bias, const float* __restrict__ Xin,
    int K, int lda, int ldb, int ldc,
    long long bsA, long long bsB, long long bsC)
{
    constexpr int WM_ = BM / 32;
    constexpr int WNT = BN / (8 / WM_);
    constexpr int NF = WNT / 8;
    constexpr int KS = BK / 16;
    constexpr int AROWS = OPA ? BK : BM;
    constexpr int ACOLS = (OPA ? BM : BK) + 8;
    constexpr int BROWS = OPB ? BN : BK;
    constexpr int BCOLS = (OPB ? BK : BN) + 8;

    extern __shared__ __align__(16) char dsm[];
    uint32_t aS = smem_u32(dsm);
    uint32_t bS = aS + (uint32_t)(2 * AROWS * ACOLS * 2);

    const int tid = threadIdx.x;
    const int warp = tid >> 5, lane = tid & 31;
    const int wm = warp % WM_, wn = warp / WM_;
    const int tr = lane & 7, tg = lane >> 3;

    const int z = blockIdx.z;
    const int n_base = blockIdx.x * BN;
    const int m_base = blockIdx.y * BM;

    long long offA = (BMODE == 1 ? (long long)(z >> 6) : (long long)z) * bsA;
    const __half* Ab = Ag + offA + (OPA ? (long long)m_base : (long long)m_base * lda);
    const __half* Bb = Bg + (long long)z * bsB + (OPB ? (long long)n_base * ldb : (long long)n_base);

    const int KT = K / BK;

    auto load_tile = [&](int st, int kt) {
        {
            constexpr int CH = (OPA ? BM : BK) / 8;
            constexpr int TOT = AROWS * CH;
#pragma unroll
            for (int c0 = 0; c0 < TOT; c0 += 256) {
                int c = c0 + tid;
                int r = c / CH, s = (c % CH) * 8;
                const __half* src = OPA ? (Ab + (long long)(kt * BK + r) * lda + s)
                                        : (Ab + (long long)r * lda + kt * BK + s);
                cp16(aS + (uint32_t)(((st * AROWS + r) * ACOLS + s) * 2), src);
            }
        }
        {
            constexpr int CH = (OPB ? BK : BN) / 8;
            constexpr int TOT = BROWS * CH;
#pragma unroll
            for (int c0 = 0; c0 < TOT; c0 += 256) {
                int c = c0 + tid;
                int r = c / CH, s = (c % CH) * 8;
                const __half* src = OPB ? (Bb + (long long)r * ldb + kt * BK + s)
                                        : (Bb + (long long)(kt * BK + r) * ldb + s);
                cp16(bS + (uint32_t)(((st * BROWS + r) * BCOLS + s) * 2), src);
            }
        }
        cp_commit();
    };

    float acc[2][NF][4];
#pragma unroll
    for (int mi = 0; mi < 2; mi++)
#pragma unroll
        for (int ni = 0; ni < NF; ni++)
#pragma unroll
            for (int j = 0; j < 4; j++) acc[mi][ni][j] = 0.f;

    load_tile(0, 0);

    for (int kt = 0; kt < KT; kt++) {
        if (kt + 1 < KT) {
            load_tile((kt + 1) & 1, kt + 1);
            asm volatile("cp.async.wait_group 1;" ::: "memory");
        } else {
            asm volatile("cp.async.wait_group 0;" ::: "memory");
        }
        __syncthreads();

        const int st = kt & 1;
#pragma unroll
        for (int ks = 0; ks < KS; ks++) {
            const int k0 = ks * 16;
            uint32_t a[2][4];
#pragma unroll
            for (int mi = 0; mi < 2; mi++) {
                int r0 = wm * 32 + mi * 16;
                if (OPA == 0) {
                    int row = r0 + tr + (tg & 1) * 8, col = k0 + (tg >> 1) * 8;
                    ldm_x4(aS + (uint32_t)(((st * AROWS + row) * ACOLS + col) * 2),
                           a[mi][0], a[mi][1], a[mi][2], a[mi][3]);
                } else {
                    int row = k0 + tr + (tg >> 1) * 8, col = r0 + (tg & 1) * 8;
                    ldm_x4t(aS + (uint32_t)(((st * AROWS + row) * ACOLS + col) * 2),
                            a[mi][0], a[mi][1], a[mi][2], a[mi][3]);
                }
            }
            uint32_t b[NF][2];
#pragma unroll
            for (int np = 0; np < NF / 2; np++) {
                int c0 = wn * WNT + np * 16;
                uint32_t q0, q1, q2, q3;
                if (OPB == 0) {
                    int row = k0 + tr + (tg & 1) * 8, col = c0 + (tg >> 1) * 8;
                    ldm_x4t(bS + (uint32_t)(((st * BROWS + row) * BCOLS + col) * 2), q0, q1, q2, q3);
                } else {
                    int row = c0 + tr + (tg >> 1) * 8, col = k0 + (tg & 1) * 8;
                    ldm_x4(bS + (uint32_t)(((st * BROWS + row) * BCOLS + col) * 2), q0, q1, q2, q3);
                }
                b[np * 2][0] = q0; b[np * 2][1] = q1;
                b[np * 2 + 1][0] = q2; b[np * 2 + 1][1] = q3;
            }
#pragma unroll
            for (int mi = 0; mi < 2; mi++)
#pragma unroll
                for (int ni = 0; ni < NF; ni++)
                    mma16816(acc[mi][ni], a[mi], b[ni]);
        }
        __syncthreads();
    }

    // ---------------- epilogue ----------------
    const float g = (EPI == 2 || EPI == 3) ? bias[0] : 0.f;
#pragma unroll
    for (int mi = 0; mi < 2; mi++) {
#pragma unroll
        for (int ni = 0; ni < NF; ni++) {
            int lr0 = wm * 32 + mi * 16 + (lane >> 2);
            int lc = wn * WNT + ni * 8 + (lane & 3) * 2;
            float* ac = acc[mi][ni];
#pragma unroll
            for (int hf = 0; hf < 2; hf++) {
                int r = lr0 + hf * 8;
                float v0 = ac[hf * 2 + 0], v1 = ac[hf * 2 + 1];
                if constexpr (EPI == 0) {
                    float* C = (float*)P0;
                    long long idx = (long long)z * bsC + (long long)(m_base + r) * ldc + n_base + lc;
                    *reinterpret_cast<float2*>(C + idx) = make_float2(v0, v1);
                } else if constexpr (EPI == 2) {
                    float* C = (float*)P0;
                    long long idx = (long long)z * bsC + (long long)(m_base + r) * ldc + n_base + lc;
                    float2 xv = *reinterpret_cast<const float2*>(Xin + idx);
                    *reinterpret_cast<float2*>(C + idx) = make_float2(3.f * xv.x + g * v0, 3.f * xv.y + g * v1);
                } else if constexpr (EPI == 3) {
                    float* C = (float*)P0;
                    long long idx = (long long)z * bsC + (long long)(m_base + r) * ldc + n_base + lc;
                    float2 cv = *reinterpret_cast<float2*>(C + idx);
                    *reinterpret_cast<float2*>(C + idx) = make_float2(cv.x + g * v0, cv.y + g * v1);
                } else if constexpr (EPI == 4) {
                    float b = bias[r];
                    __half2 hv = __floats2half2_rn(v0 + b, v1 + b);
                    int h = n_base >> 9;
                    int w = (n_base & 511) + lc;
                    long long nb = (long long)z * 2097152;
                    __half* dst;
                    if (r < 8)       dst = (__half*)P0 + nb + (long long)h * 4096 + r * 512 + w;
                    else if (r < 16) dst = (__half*)P1 + nb + (long long)h * 4096 + (r - 8) * 512 + w;
                    else if (r < 24) dst = (__half*)P2 + nb + (long long)(r - 16) * 262144 + h * 512 + w;
                    else             dst = (__half*)P3 + nb + (long long)(r - 24) * 262144 + h * 512 + w;
                    *reinterpret_cast<__half2*>(dst) = hv;
                } else if constexpr (EPI == 5) {
                    float b = bias[r];
                    __half2 hv = __floats2half2_rn(v0 + b, v1 + b);
                    long long pix = (long long)n_base + lc;
                    __half* dst = (r < 64)
                        ? ((__half*)P0 + (long long)z * 16777216 + (long long)r * 262144 + pix)
                        : ((__half*)P1 + (long long)z * 16777216 + (long long)(r - 64) * 262144 + pix);
                    *reinterpret_cast<__half2*>(dst) = hv;
                }
            }
        }
    }
}

// ---------------- host launcher ----------------
template<int BM, int BN, int BK, int OPA, int OPB, int EPI, int BMODE>
static void launch_gemm(dim3 grid,
    const __half* A, const __half* B, void* P0, void* P1, void* P2, void* P3,
    const float* bias, const float* Xin,
    int K, int lda, int ldb, int ldc, long long bsA, long long bsB, long long bsC)
{
    constexpr int AR = OPA ? BK : BM, AC = (OPA ? BM : BK) + 8;
    constexpr int BR = OPB ? BN : BK, BC = (OPB ? BK : BN) + 8;
    constexpr int sz = 4 * (AR * AC + BR * BC);
    auto kfn = k_gemm<BM, BN, BK, OPA, OPB, EPI, BMODE>;
    cudaFuncSetAttribute(kfn, cudaFuncAttributeMaxDynamicSharedMemorySize, sz);
    kfn<<<grid, 256, sz>>>(A, B, P0, P1, P2, P3, bias, Xin, K, lda, ldb, ldc, bsA, bsB, bsC);
}

extern "C" void kernel_launch(void* const* d_in, const int* in_sizes, int n_in,
                              void* d_out, int out_size)
{
    const float* x    = (const float*)d_in[0];
    const float* tq_w = (const float*)d_in[1];
    const float* tq_b = (const float*)d_in[2];
    const float* tk_w = (const float*)d_in[3];
    const float* tk_b = (const float*)d_in[4];
    const float* tv_w = (const float*)d_in[5];
    const float* tv_b = (const float*)d_in[6];
    const float* t_g  = (const float*)d_in[7];
    const float* fq_w = (const float*)d_in[8];
    const float* fq_b = (const float*)d_in[9];
    const float* fk_w = (const float*)d_in[10];
    const float* fk_b = (const float*)d_in[11];
    const float* fv_w = (const float*)d_in[12];
    const float* fv_b = (const float*)d_in[13];
    const float* f_g  = (const float*)d_in[14];
    float* out = (float*)d_out;

    __half *xh, *qt, *kt, *qf, *kf, *vt, *vf, *attn, *wqk, *wv;
    float *E, *bqk, *bv;
    cudaGetSymbolAddress((void**)&xh, g_xh);
    cudaGetSymbolAddress((void**)&qt, g_qt);
    cudaGetSymbolAddress((void**)&kt, g_kt);
    cudaGetSymbolAddress((void**)&qf, g_qf);
    cudaGetSymbolAddress((void**)&kf, g_kf);
    cudaGetSymbolAddress((void**)&vt, g_vt);
    cudaGetSymbolAddress((void**)&vf, g_vf);
    cudaGetSymbolAddress((void**)&E, g_E);
    cudaGetSymbolAddress((void**)&attn, g_attn);
    cudaGetSymbolAddress((void**)&wqk, g_wqk);
    cudaGetSymbolAddress((void**)&wv, g_wv);
    cudaGetSymbolAddress((void**)&bqk, g_bqk);
    cudaGetSymbolAddress((void**)&bv, g_bv);

    k_convert_x<<<65536, 256>>>((const float4*)x);
    k_pack_w<<<1, 256>>>(tq_w, tk_w, fq_w, fk_w, tq_b, tk_b, fq_b, fk_b,
                         tv_w, fv_w, tv_b, fv_b);

    // q/k projection for BOTH passes: M=32 stacked weights, scatter epilogue
    launch_gemm<32, 256, 64, 0, 0, 4, 0>(dim3(1024, 1, 4),
        wqk, xh, qt, kt, qf, kf, bqk, nullptr,
        64, 64, 262144, 0, 0LL, 16777216LL, 0LL);

    // v projection for BOTH passes: M=128 stacked weights
    launch_gemm<128, 128, 64, 0, 0, 5, 0>(dim3(2048, 1, 4),
        wv, xh, vt, vf, nullptr, nullptr, bv, nullptr,
        64, 64, 262144, 0, 0LL, 16777216LL, 0LL);

    // ---- time attention ----
    // energy NT: M=N=512, K=4096 (qt, kt in [n][h][c8*w])
    launch_gemm<128, 64, 64, 0, 1, 0, 0>(dim3(8, 4, 4),
        qt, kt, E, nullptr, nullptr, nullptr, nullptr, nullptr,
        4096, 4096, 4096, 512, 2097152LL, 2097152LL, 262144LL);
    k_softmax<<<2048, 256>>>();
    // out NN, batch z=(n,c): out = 3x + g*attn@v
    launch_gemm<128, 128, 64, 0, 0, 2, 1>(dim3(4, 4, 256),
        attn, vt, out, nullptr, nullptr, nullptr, t_g, x,
        512, 512, 512, 512, 262144LL, 262144LL, 262144LL);

    // ---- freq attention ----
    // energy TN: M=N=512, K=4096 (qf, kf natural layout, row stride 512)
    launch_gemm<128, 64, 64, 1, 0, 0, 0>(dim3(8, 4, 4),
        qf, kf, E, nullptr, nullptr, nullptr, nullptr, nullptr,
        4096, 512, 512, 512, 2097152LL, 2097152LL, 262144LL);
    k_softmax<<<2048, 256>>>();
    // out NT, per n: M=(c,h)=32768, N=512, K=512: out += g * v @ attn^T
    launch_gemm<128, 128, 64, 0, 1, 3, 0>(dim3(4, 256, 4),
        vf, attn, out, nullptr, nullptr, nullptr, f_g, nullptr,
        512, 512, 512, 512, 16777216LL, 262144LL, 16777216LL);
}